// round 8
// baseline (speedup 1.0000x reference)
#include <cuda_runtime.h>
#include <cuda_bf16.h>

#define IMG_H 256
#define IMG_W 256
#define NB 4
#define NK 4

#define TILE_W 32
#define TILE_H 32
#define SM_W   40          // 16B-aligned halo: cols tx0-4 .. tx0+35
#define SM_H   34          // TILE_H + 2 bottom halo (no top halo needed)
#define NVEC   (SM_W / 4)  // 10 float4 spans per row
#define GRID_BLOCKS ((IMG_W / TILE_W) * (IMG_H / TILE_H) * NB)   // 8*8*4 = 256

// Accumulators: [b][0..3] = numerator_k, [b][4..7] = denominator_k
// Zero at module load; last block resets after each run (graph-replay safe).
__device__ float        g_acc[NB][8];
__device__ unsigned int g_ticket;

// Pair-symmetric positive-direction offsets of the 21-tap mask dsq<=5.
__device__ __constant__ const int   PDY[10] = { 0, 0, 1, 1, 1, 1, 1, 2, 2, 2 };
__device__ __constant__ const int   PDX[10] = { 1, 2, -2, -1, 0, 1, 2, -1, 0, 1 };
__device__ __constant__ const float PDW[10] = {
    0.93941306f, 0.77880078f,
    0.73161563f, 0.88249690f, 0.93941306f, 0.88249690f, 0.73161563f,
    0.73161563f, 0.77880078f, 0.73161563f
};

// Per-pixel tap loop + accumulation. INTERIOR=true skips all OOB handling.
template<bool INTERIOR>
__device__ __forceinline__ void do_pixel(
    const float (*sgray)[SM_W], const float4 (*senc)[SM_W],
    int ly, int lx, int gy, int gx, float* acc)
{
    const float  c  = sgray[ly][lx];
    const float4 ec = senc [ly][lx];

    float wsum = 0.0f;
    float4 nom = make_float4(0.f, 0.f, 0.f, 0.f);
    #pragma unroll
    for (int p = 0; p < 10; p++) {
        float g  = sgray[ly + PDY[p]][lx + PDX[p]];
        float d  = g - c;
        // w = DW*exp(-d^2/100) ~= DW*(1 - 0.01 d^2); |abs err| <= 5e-5
        float w = fmaf(d * d, PDW[p] * -0.01f, PDW[p]);
        wsum += w;
        float4 e = senc[ly + PDY[p]][lx + PDX[p]];
        nom.x = fmaf(w, e.x, nom.x);
        nom.y = fmaf(w, e.y, nom.y);
        nom.z = fmaf(w, e.z, nom.z);
        nom.w = fmaf(w, e.w, nom.w);
    }

    float wd;
    if (INTERIOR) {
        wd = wsum + 1.0f;
    } else {
        // Negative-direction OOB taps: pixels with gy<2 || gx<2 || gx>253.
        // Neighbor gray is 0 => factor exp(-c^2/100); sum spatial weights.
        float S = 0.0f;
        if (gy < 2 || gx < 2 || gx > IMG_W - 3) {
            #pragma unroll
            for (int p = 0; p < 10; p++) {
                int ny = gy - PDY[p];
                int nx = gx - PDX[p];
                if (ny < 0 || (unsigned)nx >= (unsigned)IMG_W) S += PDW[p];
            }
        }
        wd = wsum + fmaf(S, fmaf(c * c, -0.01f, 1.0f), 1.0f);
    }

    // num: ec o (2*nom) [both sides of pairs] + ec o ec [center tap]
    acc[0] = fmaf(ec.x, fmaf(2.0f, nom.x, ec.x), acc[0]);
    acc[1] = fmaf(ec.y, fmaf(2.0f, nom.y, ec.y), acc[1]);
    acc[2] = fmaf(ec.z, fmaf(2.0f, nom.z, ec.z), acc[2]);
    acc[3] = fmaf(ec.w, fmaf(2.0f, nom.w, ec.w), acc[3]);
    // den: ec*(pair weights + center + OOB) + nom (e_j side of pairs)
    acc[4] += fmaf(ec.x, wd, nom.x);
    acc[5] += fmaf(ec.y, wd, nom.y);
    acc[6] += fmaf(ec.z, wd, nom.z);
    acc[7] += fmaf(ec.w, wd, nom.w);
}

__global__ __launch_bounds__(256, 2)
void sncl_fused_kernel(const float* __restrict__ image,
                       const float* __restrict__ enc,
                       float* __restrict__ out) {
    const int b   = blockIdx.z;
    const int tx0 = blockIdx.x * TILE_W;
    const int ty0 = blockIdx.y * TILE_H;

    __shared__ float  sgray[SM_H][SM_W];
    __shared__ float4 senc [SM_H][SM_W];
    __shared__ float  part [8][8];

    const int tid = threadIdx.y * 32 + threadIdx.x;
    const float* img0 = image + (size_t)b * 3 * IMG_H * IMG_W;
    const float* e0   = enc   + (size_t)b * 4 * IMG_H * IMG_W;
    const int HW = IMG_H * IMG_W;

    // Vectorized halo load: 34 rows x 10 float4-spans = 340 cells.
    // Span fully inside [0,256) or fully outside (16B aligned). OOB => 0.
    #pragma unroll
    for (int i = tid; i < SM_H * NVEC; i += 256) {
        int r  = i / NVEC;
        int v  = i - r * NVEC;
        int gy = ty0 + r;
        int gx = tx0 - 4 + v * 4;

        float4 i0 = make_float4(0.f,0.f,0.f,0.f), i1 = i0, i2 = i0;
        float4 c0 = i0, c1 = i0, c2 = i0, c3 = i0;
        if (gy < IMG_H && (unsigned)gx < (unsigned)IMG_W) {
            int off = gy * IMG_W + gx;
            i0 = *(const float4*)(img0 + off);
            i1 = *(const float4*)(img0 + HW + off);
            i2 = *(const float4*)(img0 + 2 * HW + off);
            c0 = *(const float4*)(e0 + off);
            c1 = *(const float4*)(e0 + HW + off);
            c2 = *(const float4*)(e0 + 2 * HW + off);
            c3 = *(const float4*)(e0 + 3 * HW + off);
        }
        float4 g4;
        g4.x = (i0.x + i1.x + i2.x) * (1.0f / 3.0f);
        g4.y = (i0.y + i1.y + i2.y) * (1.0f / 3.0f);
        g4.z = (i0.z + i1.z + i2.z) * (1.0f / 3.0f);
        g4.w = (i0.w + i1.w + i2.w) * (1.0f / 3.0f);
        *(float4*)&sgray[r][v * 4] = g4;
        senc[r][v * 4 + 0] = make_float4(c0.x, c1.x, c2.x, c3.x);
        senc[r][v * 4 + 1] = make_float4(c0.y, c1.y, c2.y, c3.y);
        senc[r][v * 4 + 2] = make_float4(c0.z, c1.z, c2.z, c3.z);
        senc[r][v * 4 + 3] = make_float4(c0.w, c1.w, c2.w, c3.w);
    }
    __syncthreads();

    float acc[8];
    #pragma unroll
    for (int j = 0; j < 8; j++) acc[j] = 0.0f;

    // Block is interior iff no pixel has gy<2 || gx<2 || gx>253:
    // needs ty0>=2 (=> blockIdx.y>=1), tx0>=2 (=> blockIdx.x>=1), tx0+31<=253
    // (=> blockIdx.x<=6).
    const bool interior = (blockIdx.y > 0) & (blockIdx.x > 0) &
                          (blockIdx.x < (IMG_W / TILE_W) - 1);

    if (interior) {
        #pragma unroll
        for (int half = 0; half < 4; half++) {
            const int ly = threadIdx.y + half * 8;
            do_pixel<true>(sgray, senc, ly, threadIdx.x + 4, 0, 0, acc);
        }
    } else {
        #pragma unroll
        for (int half = 0; half < 4; half++) {
            const int ly = threadIdx.y + half * 8;
            do_pixel<false>(sgray, senc, ly, threadIdx.x + 4,
                            ty0 + ly, tx0 + threadIdx.x, acc);
        }
    }

    // Warp shuffle reduce (blockDim.x == 32, warp == threadIdx.y)
    #pragma unroll
    for (int o = 16; o > 0; o >>= 1) {
        #pragma unroll
        for (int j = 0; j < 8; j++)
            acc[j] += __shfl_down_sync(0xffffffffu, acc[j], o);
    }
    if (threadIdx.x == 0) {
        #pragma unroll
        for (int j = 0; j < 8; j++)
            part[threadIdx.y][j] = acc[j];
    }
    __syncthreads();

    if (tid < 8) {
        float s = 0.0f;
        #pragma unroll
        for (int w = 0; w < 8; w++) s += part[w][tid];
        atomicAdd(&g_acc[b][tid], s);
    }
    __syncthreads();

    // Last-block finalize
    __shared__ bool is_last;
    if (tid == 0) {
        __threadfence();
        unsigned int old = atomicAdd(&g_ticket, 1u);
        is_last = (old == (unsigned int)(GRID_BLOCKS - 1));
    }
    __syncthreads();

    if (is_last && tid == 0) {
        __threadfence();
        float total = 0.0f;
        #pragma unroll
        for (int bb = 0; bb < NB; bb++) {
            float s = 0.0f;
            #pragma unroll
            for (int k = 0; k < NK; k++)
                s += g_acc[bb][k] / (g_acc[bb][4 + k] + 1e-8f);
            total += (float)NK - s;
        }
        out[0] = total * (1.0f / NB);
        #pragma unroll
        for (int j = 0; j < NB * 8; j++) ((float*)g_acc)[j] = 0.0f;
        __threadfence();
        g_ticket = 0u;
    }
}

extern "C" void kernel_launch(void* const* d_in, const int* in_sizes, int n_in,
                              void* d_out, int out_size) {
    const float* image = (const float*)d_in[0];
    const float* enc   = (const float*)d_in[1];
    float* out = (float*)d_out;

    dim3 blk(32, 8, 1);
    dim3 grd(IMG_W / TILE_W, IMG_H / TILE_H, NB);
    sncl_fused_kernel<<<grd, blk>>>(image, enc, out);
}